// round 15
// baseline (speedup 1.0000x reference)
#include <cuda_runtime.h>
#include <cstddef>
#include <cstdint>

typedef unsigned long long ull;

#define NIMG 8192
#define ACT_STRIDE 8256            /* >= 147*56 = 8232; 16B-aligned rows */
#define GFC 56
#define NBLK_FC 147

// Transposed activations: g_actT[k][img], k in [0,400). Tail stays zero (.bss).
__device__ __align__(16) float g_actT[(size_t)400 * ACT_STRIDE];
// Pre-transposed fc weights (filled by conv blocks 0..7)
__device__ __align__(16) float g_w1T[400 * 120];
__device__ __align__(16) float g_w2T[120 * 84];

__device__ __forceinline__ void cp16(uint32_t dst, const void* src) {
    asm volatile("cp.async.cg.shared.global [%0], [%1], 16;" :: "r"(dst), "l"(src));
}
#define CP_COMMIT() asm volatile("cp.async.commit_group;")
#define CP_WAIT1()  asm volatile("cp.async.wait_group 1;")

__device__ __forceinline__ void fma2(ull& d, ull a, ull b) {
    asm("fma.rn.f32x2 %0,%1,%2,%3;" : "=l"(d) : "l"(a), "l"(b), "l"(d));
}
__device__ __forceinline__ float2 up2(ull v) {
    float2 r; asm("mov.b64 {%0,%1},%2;" : "=f"(r.x), "=f"(r.y) : "l"(v)); return r;
}

// ---------------------------------------------------------------------------
// Kernel 1: fused conv1->relu->pool1->conv2->relu->pool2, IMAGE-PAIR per warp.
// 1024 blocks x 128 threads (4 warps = 8 images). All conv FMAs are
// fma.rn.f32x2 over an image pair: patches stored interleaved float2 in smem
// (packed operands free via LDS.64), weights pre-broadcast-packed float2.
// Halves the FFMA instruction count vs scalar.
// ---------------------------------------------------------------------------
__global__ __launch_bounds__(128) void conv_kernel(const float* __restrict__ x,
                                                   const float* __restrict__ w1,
                                                   const float* __restrict__ w2,
                                                   const float* __restrict__ fw1,
                                                   const float* __restrict__ fw2)
{
    extern __shared__ __align__(16) float2 sm2[];
    float2* s_w1p = sm2;                 // 456  (450 used, both halves = w)
    float2* s_w2p = sm2 + 456;           // 2400
    float2* s_b1  = sm2 + 2856;          // 4 x 768: patch [3][16][16] -> p1 [6][10][12]
    float2* s_b2  = sm2 + 2856 + 4*768;  // 4 x 880: c1 [6][12][12] -> c2 [16][6][8]
    float*  s_out = (float*)(sm2 + 2856 + 4*768 + 4*880);   // [400][8]

    const int tid  = threadIdx.x;
    const int wid  = tid >> 5;
    const int lane = tid & 31;
    const int b    = blockIdx.x;
    const int imgA = b * 8 + wid * 2;

    // broadcast-packed weights
    for (int i = tid; i < 450; i += 128) { float v = w1[i]; s_w1p[i] = make_float2(v, v); }
    for (int i = tid; i < 2400; i += 128) { float v = w2[i]; s_w2p[i] = make_float2(v, v); }

    // side-job: fc weight transposes (blocks 0..7)
    if (b < 8) {
        for (int j = b * 6000 + tid; j < (b + 1) * 6000; j += 128) {
            int o = j % 120, k = j / 120;
            g_w1T[k * 120 + o] = fw1[o * 400 + k];
        }
        for (int j = b * 1260 + tid; j < (b + 1) * 1260; j += 128) {
            int o = j % 84, k = j / 84;
            g_w2T[k * 84 + o] = fw2[o * 120 + k];
        }
    }

    float2* P = s_b1 + wid * 768;    // patch, later p1
    float2* C = s_b2 + wid * 880;    // c1, later c2

    // interleaved patch load: P[i] = (imgA[i'], imgB[i'])
    const float* xa = x + (size_t)imgA * 3072;
    const float* xb = xa + 3072;
    for (int i = lane; i < 768; i += 32) {
        int c  = i >> 8;
        int rr = (i >> 4) & 15;
        int cc = i & 15;
        int gi = c * 1024 + rr * 32 + cc;
        P[i] = make_float2(xa[gi], xb[gi]);
    }
    __syncthreads();   // weights ready (also covers patch for this warp)

    // ---- conv1 + relu: 96 tasks (3 exact passes), each 3x3 outputs, packed
    #pragma unroll
    for (int pass = 0; pass < 3; pass++) {
        int u   = lane + pass * 32;
        int oc  = u >> 4;
        int rem = u & 15;
        int r0  = (rem >> 2) * 3;
        int c0  = (rem & 3) * 3;
        ull acc[3][3];
        #pragma unroll
        for (int i = 0; i < 3; i++)
            #pragma unroll
            for (int j = 0; j < 3; j++) acc[i][j] = 0ull;

        for (int c = 0; c < 3; c++) {
            ull wreg[25];
            const ull* wb = reinterpret_cast<const ull*>(&s_w1p[(oc * 3 + c) * 25]);
            #pragma unroll
            for (int i = 0; i < 25; i++) wreg[i] = wb[i];
            const ull* Ac = reinterpret_cast<const ull*>(&P[c * 256]);
            #pragma unroll
            for (int rr = 0; rr < 7; rr++) {
                ull p[7];
                const ull* pr = &Ac[(r0 + rr) * 16 + c0];
                #pragma unroll
                for (int j = 0; j < 7; j++) p[j] = pr[j];
                #pragma unroll
                for (int orow = 0; orow < 3; orow++) {
                    int uu = rr - orow;
                    if (uu >= 0 && uu < 5) {
                        #pragma unroll
                        for (int v = 0; v < 5; v++) {
                            ull w = wreg[uu * 5 + v];
                            #pragma unroll
                            for (int j = 0; j < 3; j++)
                                fma2(acc[orow][j], p[v + j], w);
                        }
                    }
                }
            }
        }
        #pragma unroll
        for (int orow = 0; orow < 3; orow++)
            #pragma unroll
            for (int j = 0; j < 3; j++) {
                float2 v = up2(acc[orow][j]);
                C[(oc * 12 + r0 + orow) * 12 + c0 + j] =
                    make_float2(fmaxf(v.x, 0.f), fmaxf(v.y, 0.f));
            }
    }
    __syncwarp();

    // ---- pool1 (stride-1 2x2, top-left 10x10) -> P as p1[6][10][12] (patch dead)
    for (int t = lane; t < 600; t += 32) {
        int oc = t / 100;
        int rr = (t % 100) / 10;
        int cc = t % 10;
        const float2* c1 = &C[(oc * 12 + rr) * 12 + cc];
        float2 a = c1[0], bb = c1[1], cN = c1[12], d = c1[13];
        P[(oc * 10 + rr) * 12 + cc] =
            make_float2(fmaxf(fmaxf(a.x, bb.x), fmaxf(cN.x, d.x)),
                        fmaxf(fmaxf(a.y, bb.y), fmaxf(cN.y, d.y)));
    }
    __syncwarp();

    // ---- conv2 + relu: 32 tasks = oc(16) x rowhalf(2), packed -> C as c2[16][6][8]
    {
        int oc = lane >> 1;
        int r0 = (lane & 1) * 3;
        ull acc[3][6];
        #pragma unroll
        for (int i = 0; i < 3; i++)
            #pragma unroll
            for (int j = 0; j < 6; j++) acc[i][j] = 0ull;

        for (int c = 0; c < 6; c++) {
            ull wreg[25];
            const ull* wb = reinterpret_cast<const ull*>(&s_w2p[(oc * 6 + c) * 25]);
            #pragma unroll
            for (int i = 0; i < 25; i++) wreg[i] = wb[i];
            #pragma unroll
            for (int rr = 0; rr < 7; rr++) {
                const ull* pr = reinterpret_cast<const ull*>(&P[(c * 10 + r0 + rr) * 12]);
                ull p[10];
                #pragma unroll
                for (int j = 0; j < 10; j++) p[j] = pr[j];
                #pragma unroll
                for (int orow = 0; orow < 3; orow++) {
                    int uu = rr - orow;
                    if (uu >= 0 && uu < 5) {
                        #pragma unroll
                        for (int v = 0; v < 5; v++) {
                            ull w = wreg[uu * 5 + v];
                            #pragma unroll
                            for (int j = 0; j < 6; j++)
                                fma2(acc[orow][j], p[v + j], w);
                        }
                    }
                }
            }
        }
        #pragma unroll
        for (int orow = 0; orow < 3; orow++)
            #pragma unroll
            for (int j = 0; j < 6; j++) {
                float2 v = up2(acc[orow][j]);
                C[(oc * 6 + r0 + orow) * 8 + j] =
                    make_float2(fmaxf(v.x, 0.f), fmaxf(v.y, 0.f));
            }
    }
    __syncwarp();

    // ---- pool2 -> s_out[k][8] (unpack pair into adjacent image slots)
    for (int t = lane; t < 400; t += 32) {
        int oc = t / 25;
        int rr = (t % 25) / 5;
        int cc = t % 5;
        const float2* c2 = &C[(oc * 6 + rr) * 8 + cc];
        float2 a = c2[0], bb = c2[1], cN = c2[8], d = c2[9];
        s_out[t * 8 + wid * 2]     = fmaxf(fmaxf(a.x, bb.x), fmaxf(cN.x, d.x));
        s_out[t * 8 + wid * 2 + 1] = fmaxf(fmaxf(a.y, bb.y), fmaxf(cN.y, d.y));
    }
    __syncthreads();

    // ---- coalesced transposed store (img0 multiple of 8)
    const int img0 = b * 8;
    for (int k = tid; k < 400; k += 128) {
        float4 v0 = *reinterpret_cast<const float4*>(&s_out[k * 8]);
        float4 v1 = *reinterpret_cast<const float4*>(&s_out[k * 8 + 4]);
        float* dst = &g_actT[(size_t)k * ACT_STRIDE + img0];
        *reinterpret_cast<float4*>(dst)     = v0;
        *reinterpret_cast<float4*>(dst + 4) = v1;
    }
}

// ---------------------------------------------------------------------------
// Kernel 2: fused fc1(relu) -> fc2(relu) -> fc3 (R13, unchanged).
// 147 blocks x 512 threads; K-split by 2; cp.async-staged chunks of 80.
// ---------------------------------------------------------------------------
#define WCH 80
#define NCH 5
#define AROW 56
#define WROW 124
#define STGF (WCH * AROW + WCH * WROW)   /* 14400 floats per stage */

__global__ __launch_bounds__(512) void fc_kernel(const float* __restrict__ fb1,
                                                 const float* __restrict__ fb2,
                                                 const float* __restrict__ fw3,
                                                 const float* __restrict__ fb3,
                                                 float* __restrict__ out)
{
    extern __shared__ __align__(16) float sm[];
    float* s_stg  = sm;                      // 2 x 14400 = 28800
    float* s_h1T  = sm + 2 * STGF;           // [120][56] = 6720
    float* s_w2T  = s_h1T + 120 * GFC;       // [120][84] = 10080
    float* s_w3   = s_w2T + 120 * 84;        // 840
    float* s_b1   = s_w3 + 840;              // 120
    float* s_b2   = s_b1 + 120;              // 84
    float* s_b3   = s_b2 + 84;               // 12 (pad)
    float* s_h2   = sm;                      // alias after fc1: [56][84]

    const int tid  = threadIdx.x;
    const int img0 = blockIdx.x * GFC;
    const int g    = tid >> 8;
    const int sub  = tid & 255;

    const uint32_t s_base = (uint32_t)__cvta_generic_to_shared(sm);

    auto stage = [&](int ch) {
        const int buf = (ch & 1) * STGF;
        const size_t kc = (size_t)ch * WCH;
        for (int j = tid; j < 3520; j += 512) {
            if (j < 1120) {
                int row = j / 14, seg = (j % 14) * 4;
                cp16(s_base + (uint32_t)(buf + row * AROW + seg) * 4,
                     &g_actT[(kc + row) * ACT_STRIDE + img0 + seg]);
            } else {
                int q = j - 1120;
                int row = q / 30, seg = (q % 30) * 4;
                cp16(s_base + (uint32_t)(buf + WCH * AROW + row * WROW + seg) * 4,
                     &g_w1T[(kc + row) * 120 + seg]);
            }
        }
    };

    stage(0); CP_COMMIT();
    stage(1);
    for (int j = tid; j < 2520; j += 512)
        cp16(s_base + (uint32_t)(2 * STGF + 6720 + j * 4) * 4, &g_w2T[j * 4]);
    CP_COMMIT();
    for (int i = tid; i < 840; i += 512) s_w3[i] = fw3[i];
    if (tid < 120) s_b1[tid] = fb1[tid];
    else if (tid < 204) s_b2[tid - 120] = fb2[tid - 120];
    else if (tid < 214) s_b3[tid - 204] = fb3[tid - 204];
    CP_WAIT1();
    __syncthreads();

    const int o0 = (sub % 30) * 4;
    const int i0 = (sub / 30) * 8;
    const bool active = (sub < 210);
    const int kofs = g * (WCH / 2);
    float acc[8][4];
    #pragma unroll
    for (int i = 0; i < 8; i++)
        #pragma unroll
        for (int j = 0; j < 4; j++) acc[i][j] = 0.f;

    for (int ch = 0; ch < NCH; ch++) {
        const float* abuf = s_stg + (ch & 1) * STGF + kofs * AROW;
        const float* wbuf = s_stg + (ch & 1) * STGF + WCH * AROW + kofs * WROW;
        if (active) {
            #pragma unroll 5
            for (int kk = 0; kk < WCH / 2; kk++) {
                float4 w  = *reinterpret_cast<const float4*>(&wbuf[kk * WROW + o0]);
                float4 a0 = *reinterpret_cast<const float4*>(&abuf[kk * AROW + i0]);
                float4 a1 = *reinterpret_cast<const float4*>(&abuf[kk * AROW + i0 + 4]);
                acc[0][0] += a0.x * w.x; acc[0][1] += a0.x * w.y; acc[0][2] += a0.x * w.z; acc[0][3] += a0.x * w.w;
                acc[1][0] += a0.y * w.x; acc[1][1] += a0.y * w.y; acc[1][2] += a0.y * w.z; acc[1][3] += a0.y * w.w;
                acc[2][0] += a0.z * w.x; acc[2][1] += a0.z * w.y; acc[2][2] += a0.z * w.z; acc[2][3] += a0.z * w.w;
                acc[3][0] += a0.w * w.x; acc[3][1] += a0.w * w.y; acc[3][2] += a0.w * w.z; acc[3][3] += a0.w * w.w;
                acc[4][0] += a1.x * w.x; acc[4][1] += a1.x * w.y; acc[4][2] += a1.x * w.z; acc[4][3] += a1.x * w.w;
                acc[5][0] += a1.y * w.x; acc[5][1] += a1.y * w.y; acc[5][2] += a1.y * w.z; acc[5][3] += a1.y * w.w;
                acc[6][0] += a1.z * w.x; acc[6][1] += a1.z * w.y; acc[6][2] += a1.z * w.z; acc[6][3] += a1.z * w.w;
                acc[7][0] += a1.w * w.x; acc[7][1] += a1.w * w.y; acc[7][2] += a1.w * w.z; acc[7][3] += a1.w * w.w;
            }
        }
        __syncthreads();
        if (ch + 2 < NCH) stage(ch + 2);
        CP_COMMIT();
        CP_WAIT1();
        __syncthreads();
    }

    if (g == 0 && active) {
        #pragma unroll
        for (int oo = 0; oo < 4; oo++)
            #pragma unroll
            for (int ii = 0; ii < 8; ii++)
                s_h1T[(o0 + oo) * GFC + i0 + ii] = acc[ii][oo];
    }
    __syncthreads();
    if (g == 1 && active) {
        #pragma unroll
        for (int oo = 0; oo < 4; oo++) {
            float b = s_b1[o0 + oo];
            #pragma unroll
            for (int ii = 0; ii < 8; ii++) {
                float* p = &s_h1T[(o0 + oo) * GFC + i0 + ii];
                *p = fmaxf(*p + acc[ii][oo] + b, 0.f);
            }
        }
    }
    __syncthreads();

    {
        const bool act2 = (sub < 147);
        int oo0 = (sub % 21) * 4;
        int ii0 = (sub / 21) * 8;
        float c2[8][4];
        #pragma unroll
        for (int i = 0; i < 8; i++)
            #pragma unroll
            for (int j = 0; j < 4; j++) c2[i][j] = 0.f;
        if (act2) {
            const int k0 = g * 60;
            #pragma unroll 6
            for (int kk = 0; kk < 60; kk++) {
                int k = k0 + kk;
                float4 w  = *reinterpret_cast<const float4*>(&s_w2T[k * 84 + oo0]);
                float4 a0 = *reinterpret_cast<const float4*>(&s_h1T[k * GFC + ii0]);
                float4 a1 = *reinterpret_cast<const float4*>(&s_h1T[k * GFC + ii0 + 4]);
                c2[0][0] += a0.x * w.x; c2[0][1] += a0.x * w.y; c2[0][2] += a0.x * w.z; c2[0][3] += a0.x * w.w;
                c2[1][0] += a0.y * w.x; c2[1][1] += a0.y * w.y; c2[1][2] += a0.y * w.z; c2[1][3] += a0.y * w.w;
                c2[2][0] += a0.z * w.x; c2[2][1] += a0.z * w.y; c2[2][2] += a0.z * w.z; c2[2][3] += a0.z * w.w;
                c2[3][0] += a0.w * w.x; c2[3][1] += a0.w * w.y; c2[3][2] += a0.w * w.z; c2[3][3] += a0.w * w.w;
                c2[4][0] += a1.x * w.x; c2[4][1] += a1.x * w.y; c2[4][2] += a1.x * w.z; c2[4][3] += a1.x * w.w;
                c2[5][0] += a1.y * w.x; c2[5][1] += a1.y * w.y; c2[5][2] += a1.y * w.z; c2[5][3] += a1.y * w.w;
                c2[6][0] += a1.z * w.x; c2[6][1] += a1.z * w.y; c2[6][2] += a1.z * w.z; c2[6][3] += a1.z * w.w;
                c2[7][0] += a1.w * w.x; c2[7][1] += a1.w * w.y; c2[7][2] += a1.w * w.z; c2[7][3] += a1.w * w.w;
            }
        }
        __syncthreads();
        if (g == 0 && act2) {
            #pragma unroll
            for (int ii = 0; ii < 8; ii++)
                #pragma unroll
                for (int oo = 0; oo < 4; oo++)
                    s_h2[(ii0 + ii) * 84 + oo0 + oo] = c2[ii][oo];
        }
        __syncthreads();
        if (g == 1 && act2) {
            #pragma unroll
            for (int ii = 0; ii < 8; ii++)
                #pragma unroll
                for (int oo = 0; oo < 4; oo++) {
                    float* p = &s_h2[(ii0 + ii) * 84 + oo0 + oo];
                    *p = fmaxf(*p + c2[ii][oo] + s_b2[oo0 + oo], 0.f);
                }
        }
    }
    __syncthreads();

    for (int t = tid; t < GFC * 10; t += 512) {
        int o  = t % 10;
        int im = t / 10;
        float a = s_b3[o];
        #pragma unroll
        for (int k = 0; k < 84; k += 4) {
            float4 h = *reinterpret_cast<const float4*>(&s_h2[im * 84 + k]);
            float4 w = *reinterpret_cast<const float4*>(&s_w3[o * 84 + k]);
            a += h.x * w.x + h.y * w.y + h.z * w.z + h.w * w.w;
        }
        int gimg = img0 + im;
        if (gimg < NIMG) out[gimg * 10 + o] = a;
    }
}

extern "C" void kernel_launch(void* const* d_in, const int* in_sizes, int n_in,
                              void* d_out, int out_size)
{
    const float* x   = (const float*)d_in[0];
    const float* w1  = (const float*)d_in[1];
    const float* w2  = (const float*)d_in[2];
    const float* fw1 = (const float*)d_in[3];
    const float* fb1 = (const float*)d_in[4];
    const float* fw2 = (const float*)d_in[5];
    const float* fb2 = (const float*)d_in[6];
    const float* fw3 = (const float*)d_in[7];
    const float* fb3 = (const float*)d_in[8];
    float* out = (float*)d_out;

    const int CONV_SMEM = (456 + 2400 + 4 * 768 + 4 * 880) * 8 + 3200 * 4;
    const int FC_SMEM = (2 * STGF + 120 * GFC + 120 * 84 + 840 + 120 + 84 + 12) *
                        (int)sizeof(float);
    cudaFuncSetAttribute(conv_kernel, cudaFuncAttributeMaxDynamicSharedMemorySize,
                         CONV_SMEM);
    cudaFuncSetAttribute(fc_kernel, cudaFuncAttributeMaxDynamicSharedMemorySize,
                         FC_SMEM);

    conv_kernel<<<NIMG / 8, 128, CONV_SMEM>>>(x, w1, w2, fw1, fw2);
    fc_kernel<<<NBLK_FC, 512, FC_SMEM>>>(fb1, fb2, fw3, fb3, out);
}

// round 17
// speedup vs baseline: 1.0806x; 1.0806x over previous
#include <cuda_runtime.h>
#include <cstddef>
#include <cstdint>

#define NIMG 8192
#define ACT_STRIDE 8256            /* >= 294*28 = 8232; 16B-aligned rows */
#define GFC 28
#define NBLK_FC 294

// Transposed activations: g_actT[k][img], k in [0,400). Tail stays zero (.bss).
__device__ __align__(16) float g_actT[(size_t)400 * ACT_STRIDE];
// Pre-transposed fc weights (filled by conv blocks 0..7)
__device__ __align__(16) float g_w1T[400 * 120];
__device__ __align__(16) float g_w2T[120 * 84];

__device__ __forceinline__ void cp16(uint32_t dst, const void* src) {
    asm volatile("cp.async.cg.shared.global [%0], [%1], 16;" :: "r"(dst), "l"(src));
}
#define CP_COMMIT() asm volatile("cp.async.commit_group;")
#define CP_WAIT1()  asm volatile("cp.async.wait_group 1;")

// ---------------------------------------------------------------------------
// Kernel 1: fused conv1->relu->pool1->conv2->relu->pool2 (R13 version, proven).
// 1024 blocks x 256 threads, warp-per-image. Blocks 0..7 also transpose the
// fc weights into g_w1T/g_w2T.
// ---------------------------------------------------------------------------
__global__ __launch_bounds__(256) void conv_kernel(const float* __restrict__ x,
                                                   const float* __restrict__ w1,
                                                   const float* __restrict__ w2,
                                                   const float* __restrict__ fw1,
                                                   const float* __restrict__ fw2)
{
    __shared__ __align__(16) float s_w1[456];
    __shared__ __align__(16) float s_w2[2400];
    __shared__ __align__(16) float s_A[8][768];
    __shared__ __align__(16) float s_B[8][880];
    __shared__ __align__(16) float s_out[3200];

    const int tid  = threadIdx.x;
    const int wid  = tid >> 5;
    const int lane = tid & 31;
    const int img  = blockIdx.x * 8 + wid;

    for (int i = tid; i < 450; i += 256) s_w1[i] = w1[i];
    for (int i = tid; i < 2400; i += 256) s_w2[i] = w2[i];
    __syncthreads();

    float* A = s_A[wid];
    float* B = s_B[wid];

    const float* xb = x + (size_t)img * 3072;
    for (int i = lane; i < 768; i += 32) {
        int c  = i >> 8;
        int rr = (i >> 4) & 15;
        int cc = i & 15;
        A[i] = xb[c * 1024 + rr * 32 + cc];
    }
    __syncwarp();

    // conv1 + relu: 96 tasks, each 3x3 outputs; sliding-row form
    #pragma unroll
    for (int pass = 0; pass < 3; pass++) {
        int u   = lane + pass * 32;
        int oc  = u >> 4;
        int rem = u & 15;
        int r0  = (rem >> 2) * 3;
        int c0  = (rem & 3) * 3;
        float acc[3][3];
        #pragma unroll
        for (int i = 0; i < 3; i++)
            #pragma unroll
            for (int j = 0; j < 3; j++) acc[i][j] = 0.f;

        for (int c = 0; c < 3; c++) {
            float wreg[25];
            const float* wb = &s_w1[(oc * 3 + c) * 25];
            #pragma unroll
            for (int i = 0; i < 25; i++) wreg[i] = wb[i];
            const float* Ac = &A[c * 256];
            #pragma unroll
            for (int rr = 0; rr < 7; rr++) {
                float p[7];
                const float* pr = &Ac[(r0 + rr) * 16 + c0];
                #pragma unroll
                for (int j = 0; j < 7; j++) p[j] = pr[j];
                #pragma unroll
                for (int orow = 0; orow < 3; orow++) {
                    int uu = rr - orow;
                    if (uu >= 0 && uu < 5) {
                        #pragma unroll
                        for (int v = 0; v < 5; v++) {
                            float w = wreg[uu * 5 + v];
                            #pragma unroll
                            for (int j = 0; j < 3; j++)
                                acc[orow][j] += p[v + j] * w;
                        }
                    }
                }
            }
        }
        #pragma unroll
        for (int orow = 0; orow < 3; orow++)
            #pragma unroll
            for (int j = 0; j < 3; j++)
                B[(oc * 12 + r0 + orow) * 12 + c0 + j] = fmaxf(acc[orow][j], 0.f);
    }
    __syncwarp();

    for (int t = lane; t < 600; t += 32) {
        int oc = t / 100;
        int rr = (t % 100) / 10;
        int cc = t % 10;
        const float* c1 = &B[(oc * 12 + rr) * 12 + cc];
        A[(oc * 10 + rr) * 12 + cc] = fmaxf(fmaxf(c1[0], c1[1]), fmaxf(c1[12], c1[13]));
    }
    __syncwarp();

    // conv2 + relu: 32 tasks = oc(16) x rowhalf(2), weights in regs
    {
        int oc = lane >> 1;
        int r0 = (lane & 1) * 3;
        float acc[3][6];
        #pragma unroll
        for (int i = 0; i < 3; i++)
            #pragma unroll
            for (int j = 0; j < 6; j++) acc[i][j] = 0.f;

        for (int c = 0; c < 6; c++) {
            float wreg[25];
            const float* wb = &s_w2[(oc * 6 + c) * 25];
            #pragma unroll
            for (int i = 0; i < 25; i++) wreg[i] = wb[i];
            #pragma unroll
            for (int rr = 0; rr < 7; rr++) {
                const float* pr = &A[(c * 10 + r0 + rr) * 12];
                float p[10];
                float4 v0 = *reinterpret_cast<const float4*>(&pr[0]);
                float4 v1 = *reinterpret_cast<const float4*>(&pr[4]);
                p[0] = v0.x; p[1] = v0.y; p[2] = v0.z; p[3] = v0.w;
                p[4] = v1.x; p[5] = v1.y; p[6] = v1.z; p[7] = v1.w;
                p[8] = pr[8]; p[9] = pr[9];
                #pragma unroll
                for (int orow = 0; orow < 3; orow++) {
                    int uu = rr - orow;
                    if (uu >= 0 && uu < 5) {
                        #pragma unroll
                        for (int v = 0; v < 5; v++) {
                            float w = wreg[uu * 5 + v];
                            #pragma unroll
                            for (int j = 0; j < 6; j++)
                                acc[orow][j] += p[v + j] * w;
                        }
                    }
                }
            }
        }
        #pragma unroll
        for (int orow = 0; orow < 3; orow++)
            #pragma unroll
            for (int j = 0; j < 6; j++)
                B[(oc * 6 + r0 + orow) * 8 + j] = fmaxf(acc[orow][j], 0.f);
    }
    __syncwarp();

    for (int t = lane; t < 400; t += 32) {
        int oc = t / 25;
        int rr = (t % 25) / 5;
        int cc = t % 5;
        const float* c2 = &B[(oc * 6 + rr) * 8 + cc];
        s_out[t * 8 + wid] = fmaxf(fmaxf(c2[0], c2[1]), fmaxf(c2[8], c2[9]));
    }
    __syncthreads();

    const int img0 = blockIdx.x * 8;
    for (int k = tid; k < 400; k += 256) {
        float4 v0 = *reinterpret_cast<const float4*>(&s_out[k * 8]);
        float4 v1 = *reinterpret_cast<const float4*>(&s_out[k * 8 + 4]);
        float* dst = &g_actT[(size_t)k * ACT_STRIDE + img0];
        *reinterpret_cast<float4*>(dst)     = v0;
        *reinterpret_cast<float4*>(dst + 4) = v1;
    }

    // side-job: fc weight transposes (blocks 0..7)
    if (blockIdx.x < 8) {
        const int b = blockIdx.x;
        for (int j = b * 6000 + tid; j < (b + 1) * 6000; j += 256) {
            int o = j % 120, k = j / 120;
            g_w1T[k * 120 + o] = fw1[o * 400 + k];
        }
        for (int j = b * 1260 + tid; j < (b + 1) * 1260; j += 256) {
            int o = j % 84, k = j / 84;
            g_w2T[k * 84 + o] = fw2[o * 120 + k];
        }
    }
}

// ---------------------------------------------------------------------------
// Kernel 2: fused fc1(relu) -> fc2(relu) -> fc3, K-SPLIT by 2.
// 294 blocks x 512 threads; 28 images per block; ~104 KB smem -> 2 blocks/SM
// (32 warps/SM). cp.async-staged chunks of 40, 2-buffer ring.
// ---------------------------------------------------------------------------
#define WCH 40
#define NCH 10
#define AROW 28
#define WROW 124
#define STGF (WCH * AROW + WCH * WROW)   /* 6080 floats per stage */

__global__ __launch_bounds__(512, 2) void fc_kernel(const float* __restrict__ fb1,
                                                    const float* __restrict__ fb2,
                                                    const float* __restrict__ fw3,
                                                    const float* __restrict__ fb3,
                                                    float* __restrict__ out)
{
    extern __shared__ __align__(16) float sm[];
    float* s_stg  = sm;                      // 2 x 6080 = 12160
    float* s_h1T  = sm + 2 * STGF;           // [120][28] = 3360
    float* s_w2T  = s_h1T + 120 * GFC;       // [120][84] = 10080
    float* s_w3   = s_w2T + 120 * 84;        // 840
    float* s_b1   = s_w3 + 840;              // 120
    float* s_b2   = s_b1 + 120;              // 84
    float* s_b3   = s_b2 + 84;               // 12 (pad)
    float* s_h2   = sm;                      // alias after fc1: [28][84]

    const int tid  = threadIdx.x;
    const int img0 = blockIdx.x * GFC;
    const int g    = tid >> 8;     // K-group 0/1
    const int sub  = tid & 255;

    const uint32_t s_base = (uint32_t)__cvta_generic_to_shared(sm);

    // async staging of one chunk (acts: 40x7 segs, w1T: 40x30 segs)
    auto stage = [&](int ch) {
        const int buf = (ch & 1) * STGF;
        const size_t kc = (size_t)ch * WCH;
        for (int j = tid; j < 1480; j += 512) {
            if (j < 280) {
                int row = j / 7, seg = (j % 7) * 4;
                cp16(s_base + (uint32_t)(buf + row * AROW + seg) * 4,
                     &g_actT[(kc + row) * ACT_STRIDE + img0 + seg]);
            } else {
                int q = j - 280;
                int row = q / 30, seg = (q % 30) * 4;
                cp16(s_base + (uint32_t)(buf + WCH * AROW + row * WROW + seg) * 4,
                     &g_w1T[(kc + row) * 120 + seg]);
            }
        }
    };

    stage(0); CP_COMMIT();
    stage(1);
    for (int j = tid; j < 2520; j += 512)
        cp16(s_base + (uint32_t)(2 * STGF + 3360 + j * 4) * 4, &g_w2T[j * 4]);
    CP_COMMIT();
    for (int i = tid; i < 840; i += 512) s_w3[i] = fw3[i];
    if (tid < 120) s_b1[tid] = fb1[tid];
    else if (tid < 204) s_b2[tid - 120] = fb2[tid - 120];
    else if (tid < 214) s_b3[tid - 204] = fb3[tid - 204];
    CP_WAIT1();
    __syncthreads();

    // ---- fc1: [28,400] x [400,120]^T; 4img x 4out tiles; K-split halves
    const int o0 = (sub % 30) * 4;
    const int i0 = (sub / 30) * 4;
    const bool active = (sub < 210);
    const int kofs = g * (WCH / 2);   // 0 or 20 within chunk
    float acc[4][4];
    #pragma unroll
    for (int i = 0; i < 4; i++)
        #pragma unroll
        for (int j = 0; j < 4; j++) acc[i][j] = 0.f;

    for (int ch = 0; ch < NCH; ch++) {
        const float* abuf = s_stg + (ch & 1) * STGF + kofs * AROW;
        const float* wbuf = s_stg + (ch & 1) * STGF + WCH * AROW + kofs * WROW;
        if (active) {
            #pragma unroll 5
            for (int kk = 0; kk < WCH / 2; kk++) {
                float4 w = *reinterpret_cast<const float4*>(&wbuf[kk * WROW + o0]);
                float4 a = *reinterpret_cast<const float4*>(&abuf[kk * AROW + i0]);
                acc[0][0] += a.x * w.x; acc[0][1] += a.x * w.y; acc[0][2] += a.x * w.z; acc[0][3] += a.x * w.w;
                acc[1][0] += a.y * w.x; acc[1][1] += a.y * w.y; acc[1][2] += a.y * w.z; acc[1][3] += a.y * w.w;
                acc[2][0] += a.z * w.x; acc[2][1] += a.z * w.y; acc[2][2] += a.z * w.z; acc[2][3] += a.z * w.w;
                acc[3][0] += a.w * w.x; acc[3][1] += a.w * w.y; acc[3][2] += a.w * w.z; acc[3][3] += a.w * w.w;
            }
        }
        __syncthreads();
        if (ch + 2 < NCH) stage(ch + 2);
        CP_COMMIT();
        CP_WAIT1();
        __syncthreads();
    }

    // reduce K-halves: g0 stores raw, g1 adds + bias + relu
    if (g == 0 && active) {
        #pragma unroll
        for (int oo = 0; oo < 4; oo++)
            #pragma unroll
            for (int ii = 0; ii < 4; ii++)
                s_h1T[(o0 + oo) * GFC + i0 + ii] = acc[ii][oo];
    }
    __syncthreads();
    if (g == 1 && active) {
        #pragma unroll
        for (int oo = 0; oo < 4; oo++) {
            float b = s_b1[o0 + oo];
            #pragma unroll
            for (int ii = 0; ii < 4; ii++) {
                float* p = &s_h1T[(o0 + oo) * GFC + i0 + ii];
                *p = fmaxf(*p + acc[ii][oo] + b, 0.f);
            }
        }
    }
    __syncthreads();

    // ---- fc2: [28,120] x [120,84]^T; 4img x 4out tiles; K-split 60+60
    {
        const bool act2 = (sub < 147);
        int oo0 = (sub % 21) * 4;
        int ii0 = (sub / 21) * 4;
        float c2[4][4];
        #pragma unroll
        for (int i = 0; i < 4; i++)
            #pragma unroll
            for (int j = 0; j < 4; j++) c2[i][j] = 0.f;
        if (act2) {
            const int k0 = g * 60;
            #pragma unroll 6
            for (int kk = 0; kk < 60; kk++) {
                int k = k0 + kk;
                float4 w = *reinterpret_cast<const float4*>(&s_w2T[k * 84 + oo0]);
                float4 a = *reinterpret_cast<const float4*>(&s_h1T[k * GFC + ii0]);
                c2[0][0] += a.x * w.x; c2[0][1] += a.x * w.y; c2[0][2] += a.x * w.z; c2[0][3] += a.x * w.w;
                c2[1][0] += a.y * w.x; c2[1][1] += a.y * w.y; c2[1][2] += a.y * w.z; c2[1][3] += a.y * w.w;
                c2[2][0] += a.z * w.x; c2[2][1] += a.z * w.y; c2[2][2] += a.z * w.z; c2[2][3] += a.z * w.w;
                c2[3][0] += a.w * w.x; c2[3][1] += a.w * w.y; c2[3][2] += a.w * w.z; c2[3][3] += a.w * w.w;
            }
        }
        __syncthreads();   // staging buffers free -> s_h2 alias safe
        if (g == 0 && act2) {
            #pragma unroll
            for (int ii = 0; ii < 4; ii++)
                #pragma unroll
                for (int oo = 0; oo < 4; oo++)
                    s_h2[(ii0 + ii) * 84 + oo0 + oo] = c2[ii][oo];
        }
        __syncthreads();
        if (g == 1 && act2) {
            #pragma unroll
            for (int ii = 0; ii < 4; ii++)
                #pragma unroll
                for (int oo = 0; oo < 4; oo++) {
                    float* p = &s_h2[(ii0 + ii) * 84 + oo0 + oo];
                    *p = fmaxf(*p + c2[ii][oo] + s_b2[oo0 + oo], 0.f);
                }
        }
    }
    __syncthreads();

    // ---- fc3: [28,84] x [84,10]^T -> out (guarded tail)
    for (int t = tid; t < GFC * 10; t += 512) {
        int o  = t % 10;
        int im = t / 10;
        float a = s_b3[o];
        #pragma unroll
        for (int k = 0; k < 84; k += 4) {
            float4 h = *reinterpret_cast<const float4*>(&s_h2[im * 84 + k]);
            float4 w = *reinterpret_cast<const float4*>(&s_w3[o * 84 + k]);
            a += h.x * w.x + h.y * w.y + h.z * w.z + h.w * w.w;
        }
        int gimg = img0 + im;
        if (gimg < NIMG) out[gimg * 10 + o] = a;
    }
}

extern "C" void kernel_launch(void* const* d_in, const int* in_sizes, int n_in,
                              void* d_out, int out_size)
{
    const float* x   = (const float*)d_in[0];
    const float* w1  = (const float*)d_in[1];
    const float* w2  = (const float*)d_in[2];
    const float* fw1 = (const float*)d_in[3];
    const float* fb1 = (const float*)d_in[4];
    const float* fw2 = (const float*)d_in[5];
    const float* fb2 = (const float*)d_in[6];
    const float* fw3 = (const float*)d_in[7];
    const float* fb3 = (const float*)d_in[8];
    float* out = (float*)d_out;

    const int FC_SMEM = (2 * STGF + 120 * GFC + 120 * 84 + 840 + 120 + 84 + 12) *
                        (int)sizeof(float);
    cudaFuncSetAttribute(fc_kernel, cudaFuncAttributeMaxDynamicSharedMemorySize,
                         FC_SMEM);

    conv_kernel<<<NIMG / 8, 256>>>(x, w1, w2, fw1, fw2);
    fc_kernel<<<NBLK_FC, 512, FC_SMEM>>>(fb1, fb2, fw3, fb3, out);
}